// round 10
// baseline (speedup 1.0000x reference)
#include <cuda_runtime.h>
#include <cstdint>

// Sorted segment-sum: pred_rgb[r] = sum_{i in ray r} w[i] * rgb[i]
// N_SAMPLES = 4194304, N_RAYS = 65536, indices sorted ascending.
//
// R5: TMA ring (from R4) + conflict-free lane-strided consumer with
// warp-segmented reduction. R4 post-mortem: per-thread-contiguous smem
// reads had 4-8 way bank conflicts (~1790 crossbar cyc/stage) plus ~220
// sparse REDG instructions (~900 cyc) -> consume 2630 cyc/stage vs fill
// floor 1365. Now: lane=sample loads (0 conflicts, 320 cyc/stage),
// per-32-sample-group segmented reduce via shfl (fast path: uniform-ray
// butterfly; slow path: scan + subtract-at-head), ~1.5 atomic flushes
// per group. TPB=512 so per-warp issue work halves.

#define TPB          512
#define STAGE_SAMPLES 2048
#define NSTAGE       4
#define IDX_B        (STAGE_SAMPLES * 4)         // 8192
#define W_B          (STAGE_SAMPLES * 4)         // 8192
#define RGB_B        (STAGE_SAMPLES * 12)        // 24576
#define STAGE_B      (IDX_B + W_B + RGB_B)       // 40960
#define DATA_OFF     128
#define SMEM_TOTAL   (DATA_OFF + NSTAGE * STAGE_B)
#define GROUPS_PER_WARP (STAGE_SAMPLES / (TPB / 32) / 32)   // 4

__device__ __forceinline__ uint32_t smem_u32(const void* p) {
    uint32_t a;
    asm("{ .reg .u64 t; cvta.to.shared.u64 t, %1; cvt.u32.u64 %0, t; }"
        : "=r"(a) : "l"(p));
    return a;
}
__device__ __forceinline__ void mbar_init(uint32_t mbar, uint32_t count) {
    asm volatile("mbarrier.init.shared.b64 [%0], %1;" :: "r"(mbar), "r"(count) : "memory");
}
__device__ __forceinline__ void mbar_expect_tx(uint32_t mbar, uint32_t bytes) {
    asm volatile("mbarrier.arrive.expect_tx.shared.b64 _, [%0], %1;"
                 :: "r"(mbar), "r"(bytes) : "memory");
}
__device__ __forceinline__ void mbar_wait(uint32_t mbar, uint32_t parity) {
    uint32_t done;
    asm volatile(
        "{\n\t.reg .pred p;\n\t"
        "mbarrier.try_wait.parity.acquire.cta.shared::cta.b64 p, [%1], %2;\n\t"
        "selp.b32 %0, 1, 0, p;\n\t}"
        : "=r"(done) : "r"(mbar), "r"(parity) : "memory");
    if (!done) {
        asm volatile(
            "{\n\t.reg .pred P1;\n\t"
            "W_%=:\n\t"
            "mbarrier.try_wait.parity.acquire.cta.shared::cta.b64 P1, [%0], %1, 0x989680;\n\t"
            "@P1 bra.uni D_%=;\n\t"
            "bra.uni W_%=;\n\t"
            "D_%=:\n\t}"
            :: "r"(mbar), "r"(parity) : "memory");
    }
}
__device__ __forceinline__ void bulk_g2s(uint32_t dst, const void* src,
                                         uint32_t bytes, uint32_t mbar) {
    asm volatile(
        "cp.async.bulk.shared::cta.global.mbarrier::complete_tx::bytes [%0], [%1], %2, [%3];"
        :: "r"(dst), "l"(src), "r"(bytes), "r"(mbar) : "memory");
}

__global__ void zero_out_kernel(float* __restrict__ out, int n) {
    int i = (blockIdx.x * blockDim.x + threadIdx.x) * 4;
    if (i + 3 < n) {
        *reinterpret_cast<float4*>(out + i) = make_float4(0.f, 0.f, 0.f, 0.f);
    } else {
        for (int j = i; j < n; j++) out[j] = 0.f;
    }
}

__global__ __launch_bounds__(TPB, 1) void seg_sum_kernel(
    const float* __restrict__ rgb,
    const float* __restrict__ w,
    const int*   __restrict__ idx,
    float* __restrict__ out,
    int n)
{
    extern __shared__ __align__(128) char smem[];
    const int tid  = threadIdx.x;
    const int lane = tid & 31;
    const int wid  = tid >> 5;
    const uint32_t smem_base = smem_u32(smem);

    const int total_stages = n / STAGE_SAMPLES;
    const int G = gridDim.x;

    // Scalar tail (0 samples for this problem size, kept for generality).
    if (blockIdx.x == 0 && tid == 0) {
        for (long long s = (long long)total_stages * STAGE_SAMPLES; s < n; s++) {
            float wi = w[s];
            int r = idx[s];
            atomicAdd(&out[r * 3 + 0], wi * rgb[s * 3 + 0]);
            atomicAdd(&out[r * 3 + 1], wi * rgb[s * 3 + 1]);
            atomicAdd(&out[r * 3 + 2], wi * rgb[s * 3 + 2]);
        }
    }

    int nmine = 0;
    for (int g = blockIdx.x; g < total_stages; g += G) nmine++;
    if (nmine == 0) return;

    if (tid == 0) {
        #pragma unroll
        for (int s = 0; s < NSTAGE; s++) mbar_init(smem_base + s * 8, 1);
    }
    __syncthreads();

    if (tid == 0) {
        int npro = nmine < NSTAGE ? nmine : NSTAGE;
        for (int k = 0; k < npro; k++) {
            int g = blockIdx.x + k * G;
            long long base = (long long)g * STAGE_SAMPLES;
            uint32_t mb  = smem_base + k * 8;
            uint32_t dst = smem_base + DATA_OFF + k * STAGE_B;
            mbar_expect_tx(mb, STAGE_B);
            bulk_g2s(dst,               idx + base,     IDX_B, mb);
            bulk_g2s(dst + IDX_B,       w   + base,     W_B,   mb);
            bulk_g2s(dst + IDX_B + W_B, rgb + base * 3, RGB_B, mb);
        }
    }

    for (int k = 0; k < nmine; k++) {
        const int slot = k & (NSTAGE - 1);
        const uint32_t parity = (k / NSTAGE) & 1;
        mbar_wait(smem_base + slot * 8, parity);

        const char*  sd   = smem + DATA_OFF + slot * STAGE_B;
        const int*   sidx = reinterpret_cast<const int*>(sd);
        const float* sw   = reinterpret_cast<const float*>(sd + IDX_B);
        const float* srgb = reinterpret_cast<const float*>(sd + IDX_B + W_B);

        #pragma unroll
        for (int g = 0; g < GROUPS_PER_WARP; g++) {
            // Lane-strided, conflict-free smem reads (lane = sample).
            int s = wid * (GROUPS_PER_WARP * 32) + g * 32 + lane;
            int ray   = sidx[s];
            float wt  = sw[s];
            float v0  = wt * srgb[3 * s + 0];
            float v1  = wt * srgb[3 * s + 1];
            float v2  = wt * srgb[3 * s + 2];

            int ray_up = __shfl_up_sync(0xFFFFFFFFu, ray, 1);
            bool head  = (lane == 0) || (ray_up != ray);
            unsigned hb = __ballot_sync(0xFFFFFFFFu, head);

            if (hb == 1u) {
                // Entire group is one ray: butterfly reduce, lane 0 flushes.
                #pragma unroll
                for (int d = 16; d; d >>= 1) {
                    v0 += __shfl_xor_sync(0xFFFFFFFFu, v0, d);
                    v1 += __shfl_xor_sync(0xFFFFFFFFu, v1, d);
                    v2 += __shfl_xor_sync(0xFFFFFFFFu, v2, d);
                }
                if (lane == 0) {
                    atomicAdd(&out[ray * 3 + 0], v0);
                    atomicAdd(&out[ray * 3 + 1], v1);
                    atomicAdd(&out[ray * 3 + 2], v2);
                }
            } else {
                // Inclusive scans.
                #pragma unroll
                for (int d = 1; d < 32; d <<= 1) {
                    float t0 = __shfl_up_sync(0xFFFFFFFFu, v0, d);
                    float t1 = __shfl_up_sync(0xFFFFFFFFu, v1, d);
                    float t2 = __shfl_up_sync(0xFFFFFFFFu, v2, d);
                    if (lane >= d) { v0 += t0; v1 += t1; v2 += t2; }
                }
                // My segment's head lane = highest set bit of hb at <= lane.
                unsigned hmask = hb & (0xFFFFFFFFu >> (31 - lane));
                int hl = 31 - __clz(hmask);     // >= 0 (bit 0 always set)
                int src = hl > 0 ? hl - 1 : 0;
                float b0 = __shfl_sync(0xFFFFFFFFu, v0, src);
                float b1 = __shfl_sync(0xFFFFFFFFu, v1, src);
                float b2 = __shfl_sync(0xFFFFFFFFu, v2, src);
                if (hl == 0) { b0 = 0.f; b1 = 0.f; b2 = 0.f; }

                int ray_dn = __shfl_down_sync(0xFFFFFFFFu, ray, 1);
                bool end   = (lane == 31) || (ray_dn != ray);
                if (end) {
                    atomicAdd(&out[ray * 3 + 0], v0 - b0);
                    atomicAdd(&out[ray * 3 + 1], v1 - b1);
                    atomicAdd(&out[ray * 3 + 2], v2 - b2);
                }
            }
        }

        __syncthreads();   // slot fully consumed -> safe to refill

        if (tid == 0 && k + NSTAGE < nmine) {
            int g = blockIdx.x + (k + NSTAGE) * G;
            long long base = (long long)g * STAGE_SAMPLES;
            uint32_t mb  = smem_base + slot * 8;
            uint32_t dst = smem_base + DATA_OFF + slot * STAGE_B;
            mbar_expect_tx(mb, STAGE_B);
            bulk_g2s(dst,               idx + base,     IDX_B, mb);
            bulk_g2s(dst + IDX_B,       w   + base,     W_B,   mb);
            bulk_g2s(dst + IDX_B + W_B, rgb + base * 3, RGB_B, mb);
        }
    }
}

extern "C" void kernel_launch(void* const* d_in, const int* in_sizes, int n_in,
                              void* d_out, int out_size)
{
    const float* rgb = (const float*)d_in[0];
    const float* w   = (const float*)d_in[1];
    const int*   idx = (const int*)d_in[2];
    float* out = (float*)d_out;

    int n = in_sizes[2];

    cudaFuncSetAttribute(seg_sum_kernel,
                         cudaFuncAttributeMaxDynamicSharedMemorySize, SMEM_TOTAL);

    int zb = (out_size / 4 + 255) / 256;
    zero_out_kernel<<<zb, 256>>>(out, out_size);

    int total_stages = n / STAGE_SAMPLES;
    int blocks = 148;
    if (total_stages < blocks) blocks = total_stages > 0 ? total_stages : 1;
    seg_sum_kernel<<<blocks, TPB, SMEM_TOTAL>>>(rgb, w, idx, out, n);
}